// round 2
// baseline (speedup 1.0000x reference)
#include <cuda_runtime.h>
#include <cstdint>

// Problem constants (from reference): N=50000, E=1600000, F_IN=128, HID=128, F_OUT=64
#define MAXN 50000
#define MAXE 1600000
#define F_IN 128
#define HID  128
#define F_OUT 64

// Scratch (device globals — no allocations allowed)
__device__ float g_deg[MAXN];                 // degree -> dinv (rsqrt) in place
__device__ float g_h1[(size_t)MAXN * HID];    // x @ W1
__device__ float g_agg1[(size_t)MAXN * HID];  // aggregated layer-1
__device__ float g_h2[(size_t)MAXN * F_OUT];  // relu(agg1+b1) @ W2

// ---------------------------------------------------------------------------
// init: zero agg1, zero out, deg = 1 (self-loop)
__global__ void k_init(float* __restrict__ out, int n) {
    int i = blockIdx.x * blockDim.x + threadIdx.x;
    int n128 = n * HID;
    if (i < n128) g_agg1[i] = 0.f;
    if (i < n * F_OUT) out[i] = 0.f;
    if (i < n) g_deg[i] = 1.f;
}

// degree count: one thread per edge
__global__ void k_deg(const int* __restrict__ ei, int e) {
    int i = blockIdx.x * blockDim.x + threadIdx.x;
    if (i < e) atomicAdd(&g_deg[ei[e + i]], 1.0f);  // dst row
}

__global__ void k_rsqrt(int n) {
    int i = blockIdx.x * blockDim.x + threadIdx.x;
    if (i < n) g_deg[i] = rsqrtf(g_deg[i]);
}

// ---------------------------------------------------------------------------
// GEMM1: h1[n,128] = x[n,128] @ W1[128,128]
// block = 128 threads, 16 nodes per block. Thread j computes feature j for
// all 16 nodes. x tile in smem (broadcast reads), W1 rows coalesced (L1-hot).
__global__ void k_gemm1(const float* __restrict__ x, const float* __restrict__ W1, int n) {
    __shared__ float xs[16 * F_IN];
    int base = blockIdx.x * 16;
    for (int i = threadIdx.x; i < 16 * F_IN; i += 128) {
        int nn = i >> 7, k = i & 127;
        xs[i] = (base + nn < n) ? x[(size_t)(base + nn) * F_IN + k] : 0.f;
    }
    __syncthreads();
    int j = threadIdx.x;
    float acc[16];
#pragma unroll
    for (int t = 0; t < 16; t++) acc[t] = 0.f;
#pragma unroll 4
    for (int k = 0; k < F_IN; k++) {
        float w = W1[k * HID + j];
#pragma unroll
        for (int t = 0; t < 16; t++) acc[t] += xs[t * F_IN + k] * w;
    }
#pragma unroll
    for (int t = 0; t < 16; t++) {
        int node = base + t;
        if (node < n) g_h1[(size_t)node * HID + j] = acc[t];
    }
}

// ---------------------------------------------------------------------------
// Layer-1 aggregation: one warp per item (edge or self-loop).
// 32 lanes x float4 = 128 floats. Vector red.global to cut L2 atomic ops 4x.
__global__ void k_agg1(const int* __restrict__ ei, int n, int e) {
    int gt = blockIdx.x * blockDim.x + threadIdx.x;
    int w = gt >> 5, lane = gt & 31;
    int total = e + n;
    if (w >= total) return;
    int src, dst;
    if (w < e) { src = ei[w]; dst = ei[e + w]; }
    else       { src = w - e; dst = src; }
    float nrm = g_deg[src] * g_deg[dst];
    float4 v = reinterpret_cast<const float4*>(g_h1 + (size_t)src * HID)[lane];
    v.x *= nrm; v.y *= nrm; v.z *= nrm; v.w *= nrm;
    float* p = g_agg1 + (size_t)dst * HID + lane * 4;
    asm volatile("red.global.add.v4.f32 [%0], {%1,%2,%3,%4};"
                 :: "l"(p), "f"(v.x), "f"(v.y), "f"(v.z), "f"(v.w) : "memory");
}

// ---------------------------------------------------------------------------
// GEMM2 (fused bias+ReLU on input): h2[n,64] = relu(agg1+b1) @ W2[128,64]
// block = 128 threads: j = tid&63 feature, half = tid>>6 -> 8 nodes each.
__global__ void k_gemm2(const float* __restrict__ b1, const float* __restrict__ W2, int n) {
    __shared__ float xs[16 * HID];
    __shared__ float bs[HID];
    int base = blockIdx.x * 16;
    bs[threadIdx.x] = b1[threadIdx.x];
    __syncthreads();
    for (int i = threadIdx.x; i < 16 * HID; i += 128) {
        int nn = i >> 7, k = i & 127;
        float v = (base + nn < n) ? g_agg1[(size_t)(base + nn) * HID + k] + bs[k] : 0.f;
        xs[i] = fmaxf(v, 0.f);
    }
    __syncthreads();
    int j = threadIdx.x & 63;
    int half = threadIdx.x >> 6;
    float acc[8];
#pragma unroll
    for (int t = 0; t < 8; t++) acc[t] = 0.f;
#pragma unroll 4
    for (int k = 0; k < HID; k++) {
        float w = W2[k * F_OUT + j];
#pragma unroll
        for (int t = 0; t < 8; t++) acc[t] += xs[(half * 8 + t) * HID + k] * w;
    }
#pragma unroll
    for (int t = 0; t < 8; t++) {
        int node = base + half * 8 + t;
        if (node < n) g_h2[(size_t)node * F_OUT + j] = acc[t];
    }
}

// ---------------------------------------------------------------------------
// Layer-2 aggregation: warp per item, 32 lanes x float2 = 64 floats, into out.
__global__ void k_agg2(const int* __restrict__ ei, float* __restrict__ out, int n, int e) {
    int gt = blockIdx.x * blockDim.x + threadIdx.x;
    int w = gt >> 5, lane = gt & 31;
    int total = e + n;
    if (w >= total) return;
    int src, dst;
    if (w < e) { src = ei[w]; dst = ei[e + w]; }
    else       { src = w - e; dst = src; }
    float nrm = g_deg[src] * g_deg[dst];
    float2 v = reinterpret_cast<const float2*>(g_h2 + (size_t)src * F_OUT)[lane];
    v.x *= nrm; v.y *= nrm;
    float* p = out + (size_t)dst * F_OUT + lane * 2;
    asm volatile("red.global.add.v2.f32 [%0], {%1,%2};"
                 :: "l"(p), "f"(v.x), "f"(v.y) : "memory");
}

// final: out = relu(out + b2)
__global__ void k_finish(float* __restrict__ out, const float* __restrict__ b2, int n) {
    int i = blockIdx.x * blockDim.x + threadIdx.x;
    if (i < n * F_OUT) out[i] = fmaxf(out[i] + b2[i & 63], 0.f);
}

// ---------------------------------------------------------------------------
extern "C" void kernel_launch(void* const* d_in, const int* in_sizes, int n_in,
                              void* d_out, int out_size) {
    const float* x  = (const float*)d_in[0];      // [1,N,128]
    const int*   ei = (const int*)d_in[1];        // [2,E]
    const float* W1 = (const float*)d_in[2];      // [128,128]
    const float* b1 = (const float*)d_in[3];      // [128]
    const float* W2 = (const float*)d_in[4];      // [128,64]
    const float* b2 = (const float*)d_in[5];      // [64]
    float* out = (float*)d_out;                   // [N,64]

    int n = in_sizes[0] / F_IN;
    int e = in_sizes[1] / 2;

    // init (covers n*128 elements, the largest range)
    {
        int tot = n * HID;
        k_init<<<(tot + 255) / 256, 256>>>(out, n);
    }
    k_deg<<<(e + 255) / 256, 256>>>(ei, e);
    k_rsqrt<<<(n + 255) / 256, 256>>>(n);

    k_gemm1<<<(n + 15) / 16, 128>>>(x, W1, n);

    {
        long long items = (long long)e + n;
        long long threads = items * 32;
        int grid = (int)((threads + 255) / 256);
        k_agg1<<<grid, 256>>>(ei, n, e);
    }

    k_gemm2<<<(n + 15) / 16, 128>>>(b1, W2, n);

    {
        long long items = (long long)e + n;
        long long threads = items * 32;
        int grid = (int)((threads + 255) / 256);
        k_agg2<<<grid, 256>>>(ei, out, n, e);
    }

    k_finish<<<(n * F_OUT + 255) / 256, 256>>>(out, b2, n);
}

// round 3
// speedup vs baseline: 2.0607x; 2.0607x over previous
#include <cuda_runtime.h>
#include <cstdint>

#define MAXN 50000
#define MAXE 1600000
#define F_IN 128
#define HID  128
#define F_OUT 64

// ---- scratch (device globals; no allocation allowed) ----
__device__ int   g_cnt[MAXN];        // dst histogram (degree w/o self-loop)
__device__ int   g_rowtmp[MAXN];     // inclusive scan temp
__device__ int   g_bsum[256];
__device__ int   g_boff[256];
__device__ int   g_rowptr[MAXN + 1];
__device__ int   g_wp[MAXN];         // scatter write pointers
__device__ float g_dinv[MAXN];
__device__ int   g_esrc[MAXE];       // CSR: src per slot
__device__ float g_enrm[MAXE];       // CSR: norm per slot
__device__ float g_h1[(size_t)MAXN * HID];
__device__ float g_agg1[(size_t)MAXN * HID];
__device__ float g_h2[(size_t)MAXN * F_OUT];

// ---------------------------------------------------------------------------
__global__ void k_zero(int n) {
    int i = blockIdx.x * blockDim.x + threadIdx.x;
    if (i < n) g_cnt[i] = 0;
}

__global__ void k_hist(const int* __restrict__ ei, int e) {
    int i = blockIdx.x * blockDim.x + threadIdx.x;
    if (i < e) atomicAdd(&g_cnt[ei[e + i]], 1);
}

__global__ void k_dinv(int n) {
    int i = blockIdx.x * blockDim.x + threadIdx.x;
    if (i < n) g_dinv[i] = rsqrtf((float)g_cnt[i] + 1.0f);
}

// two-level exclusive scan of g_cnt -> g_rowptr
__global__ void k_scan_a(int n) {
    __shared__ int s[256];
    int i = blockIdx.x * 256 + threadIdx.x;
    int v = (i < n) ? g_cnt[i] : 0;
    s[threadIdx.x] = v;
    __syncthreads();
#pragma unroll
    for (int off = 1; off < 256; off <<= 1) {
        int t = (threadIdx.x >= off) ? s[threadIdx.x - off] : 0;
        __syncthreads();
        s[threadIdx.x] += t;
        __syncthreads();
    }
    if (i < n) g_rowtmp[i] = s[threadIdx.x];
    if (threadIdx.x == 255) g_bsum[blockIdx.x] = s[255];
}

__global__ void k_scan_b(int nblocks) {
    __shared__ int s[256];
    int v = (threadIdx.x < nblocks) ? g_bsum[threadIdx.x] : 0;
    s[threadIdx.x] = v;
    __syncthreads();
#pragma unroll
    for (int off = 1; off < 256; off <<= 1) {
        int t = (threadIdx.x >= off) ? s[threadIdx.x - off] : 0;
        __syncthreads();
        s[threadIdx.x] += t;
        __syncthreads();
    }
    g_boff[threadIdx.x] = s[threadIdx.x] - v;  // exclusive
}

__global__ void k_scan_c(int n, int e) {
    int i = blockIdx.x * 256 + threadIdx.x;
    if (i < n) {
        int rp = g_boff[blockIdx.x] + g_rowtmp[i] - g_cnt[i];
        g_rowptr[i] = rp;
        g_wp[i] = rp;
    }
    if (i == 0) g_rowptr[n] = e;
}

__global__ void k_scatter(const int* __restrict__ ei, int e) {
    int i = blockIdx.x * blockDim.x + threadIdx.x;
    if (i >= e) return;
    int src = ei[i], dst = ei[e + i];
    int pos = atomicAdd(&g_wp[dst], 1);
    g_esrc[pos] = src;
    g_enrm[pos] = g_dinv[src] * g_dinv[dst];
}

// ---------------------------------------------------------------------------
// GEMM1: h1[n,128] = x[n,128] @ W1[128,128]
// 256 thr, 64-node tile. thread = (j4 = tid&31 -> 4 feats, ng = tid>>5 -> 8 nodes)
__global__ void k_gemm1(const float* __restrict__ x, const float* __restrict__ W1, int n) {
    __shared__ float xs[64 * F_IN];
    int base = blockIdx.x * 64;
    const float4* xv = (const float4*)x;
    float4* xsv = (float4*)xs;
    for (int i = threadIdx.x; i < 64 * 32; i += 256) {
        int node = i >> 5, c = i & 31;
        xsv[i] = (base + node < n) ? xv[(size_t)(base + node) * 32 + c]
                                   : make_float4(0.f, 0.f, 0.f, 0.f);
    }
    __syncthreads();
    int j4 = threadIdx.x & 31;
    int ng = threadIdx.x >> 5;
    const float4* Wv = (const float4*)W1;
    float acc[8][4];
#pragma unroll
    for (int t = 0; t < 8; t++) { acc[t][0]=acc[t][1]=acc[t][2]=acc[t][3]=0.f; }
#pragma unroll 4
    for (int k = 0; k < F_IN; k++) {
        float4 wk = Wv[k * 32 + j4];
#pragma unroll
        for (int t = 0; t < 8; t++) {
            float xx = xs[(ng * 8 + t) * F_IN + k];
            acc[t][0] += xx * wk.x;
            acc[t][1] += xx * wk.y;
            acc[t][2] += xx * wk.z;
            acc[t][3] += xx * wk.w;
        }
    }
#pragma unroll
    for (int t = 0; t < 8; t++) {
        int node = base + ng * 8 + t;
        if (node < n)
            ((float4*)g_h1)[(size_t)node * 32 + j4] =
                make_float4(acc[t][0], acc[t][1], acc[t][2], acc[t][3]);
    }
}

// ---------------------------------------------------------------------------
// Layer-1 pull aggregation: one warp per dst node, float4 per lane, no atomics.
__global__ void k_agg1(int n) {
    int w = (blockIdx.x * blockDim.x + threadIdx.x) >> 5;
    int lane = threadIdx.x & 31;
    if (w >= n) return;
    int beg = g_rowptr[w], end = g_rowptr[w + 1];
    float di = g_dinv[w];
    const float4* base = (const float4*)g_h1;
    float4 v = base[(size_t)w * 32 + lane];
    float s = di * di;
    float4 acc = make_float4(v.x * s, v.y * s, v.z * s, v.w * s);
#pragma unroll 2
    for (int p = beg; p < end; p++) {
        int src = g_esrc[p];
        float wgt = g_enrm[p];
        float4 u = base[(size_t)src * 32 + lane];
        acc.x += wgt * u.x;
        acc.y += wgt * u.y;
        acc.z += wgt * u.z;
        acc.w += wgt * u.w;
    }
    ((float4*)g_agg1)[(size_t)w * 32 + lane] = acc;
}

// ---------------------------------------------------------------------------
// GEMM2: h2[n,64] = relu(agg1 + b1) @ W2[128,64]
// 256 thr, 64-node tile. thread = (j4 = tid&15 -> 4 feats, ng = tid>>4 -> 4 nodes)
__global__ void k_gemm2(const float* __restrict__ b1, const float* __restrict__ W2, int n) {
    __shared__ float xs[64 * HID];
    __shared__ float bs[HID];
    int base = blockIdx.x * 64;
    if (threadIdx.x < HID) bs[threadIdx.x] = b1[threadIdx.x];
    __syncthreads();
    for (int i = threadIdx.x; i < 64 * HID; i += 256) {
        int node = i >> 7, k = i & 127;
        float v = (base + node < n) ? g_agg1[(size_t)(base + node) * HID + k] + bs[k] : 0.f;
        xs[i] = fmaxf(v, 0.f);
    }
    __syncthreads();
    int j4 = threadIdx.x & 15;
    int ng = threadIdx.x >> 4;
    const float4* Wv = (const float4*)W2;
    float acc[4][4];
#pragma unroll
    for (int t = 0; t < 4; t++) { acc[t][0]=acc[t][1]=acc[t][2]=acc[t][3]=0.f; }
#pragma unroll 4
    for (int k = 0; k < HID; k++) {
        float4 wk = Wv[k * 16 + j4];
#pragma unroll
        for (int t = 0; t < 4; t++) {
            float xx = xs[(ng * 4 + t) * HID + k];
            acc[t][0] += xx * wk.x;
            acc[t][1] += xx * wk.y;
            acc[t][2] += xx * wk.z;
            acc[t][3] += xx * wk.w;
        }
    }
#pragma unroll
    for (int t = 0; t < 4; t++) {
        int node = base + ng * 4 + t;
        if (node < n)
            ((float4*)g_h2)[(size_t)node * 16 + j4] =
                make_float4(acc[t][0], acc[t][1], acc[t][2], acc[t][3]);
    }
}

// ---------------------------------------------------------------------------
// Layer-2 pull aggregation + fused bias+ReLU epilogue: warp per node, float2/lane.
__global__ void k_agg2(float* __restrict__ out, const float* __restrict__ b2, int n) {
    int w = (blockIdx.x * blockDim.x + threadIdx.x) >> 5;
    int lane = threadIdx.x & 31;
    if (w >= n) return;
    int beg = g_rowptr[w], end = g_rowptr[w + 1];
    float di = g_dinv[w];
    const float2* base = (const float2*)g_h2;
    float2 v = base[(size_t)w * 32 + lane];
    float s = di * di;
    float2 acc = make_float2(v.x * s, v.y * s);
#pragma unroll 2
    for (int p = beg; p < end; p++) {
        int src = g_esrc[p];
        float wgt = g_enrm[p];
        float2 u = base[(size_t)src * 32 + lane];
        acc.x += wgt * u.x;
        acc.y += wgt * u.y;
    }
    float bx = b2[lane * 2], by = b2[lane * 2 + 1];
    ((float2*)out)[(size_t)w * 32 + lane] =
        make_float2(fmaxf(acc.x + bx, 0.f), fmaxf(acc.y + by, 0.f));
}

// ---------------------------------------------------------------------------
extern "C" void kernel_launch(void* const* d_in, const int* in_sizes, int n_in,
                              void* d_out, int out_size) {
    const float* x  = (const float*)d_in[0];
    const int*   ei = (const int*)d_in[1];
    const float* W1 = (const float*)d_in[2];
    const float* b1 = (const float*)d_in[3];
    const float* W2 = (const float*)d_in[4];
    const float* b2 = (const float*)d_in[5];
    float* out = (float*)d_out;

    int n = in_sizes[0] / F_IN;
    int e = in_sizes[1] / 2;
    int nb = (n + 255) / 256;

    // CSR build (also yields degrees)
    k_zero<<<nb, 256>>>(n);
    k_hist<<<(e + 255) / 256, 256>>>(ei, e);
    k_dinv<<<nb, 256>>>(n);
    k_scan_a<<<nb, 256>>>(n);
    k_scan_b<<<1, 256>>>(nb);
    k_scan_c<<<nb, 256>>>(n, e);
    k_scatter<<<(e + 255) / 256, 256>>>(ei, e);

    // layer 1
    k_gemm1<<<(n + 63) / 64, 256>>>(x, W1, n);
    {
        long long thr = (long long)n * 32;
        k_agg1<<<(int)((thr + 255) / 256), 256>>>(n);
    }
    // layer 2
    k_gemm2<<<(n + 63) / 64, 256>>>(b1, W2, n);
    {
        long long thr = (long long)n * 32;
        k_agg2<<<(int)((thr + 255) / 256), 256>>>(out, b2, n);
    }
}

// round 4
// speedup vs baseline: 2.2978x; 1.1150x over previous
#include <cuda_runtime.h>
#include <cuda_fp16.h>
#include <cstdint>

#define MAXN 50000
#define MAXE 1600000
#define F_IN 128
#define HID  128
#define F_OUT 64

// ---- scratch (device globals; no allocation allowed) ----
__device__ int    g_cnt[MAXN];
__device__ int    g_rowtmp[MAXN];
__device__ int    g_bsum[256];
__device__ int    g_boff[256];
__device__ int    g_rowptr[MAXN + 1];
__device__ int    g_wp[MAXN];
__device__ float  g_dinv[MAXN];
__device__ int2   g_edge[MAXE];                 // .x = src, .y = bits(norm)
__device__ __half g_h1h[(size_t)MAXN * HID];    // fp16 copy of x@W1 (gather operand)
__device__ float  g_agg1[(size_t)MAXN * HID];   // fp32 aggregated layer-1
__device__ __half g_h2h[(size_t)MAXN * F_OUT];  // fp16 copy of layer-2 pre-agg

// ---------------------------------------------------------------------------
__global__ void k_zero(int n) {
    int i = blockIdx.x * blockDim.x + threadIdx.x;
    if (i < n) g_cnt[i] = 0;
}

__global__ void k_hist(const int* __restrict__ ei, int e) {
    int i = blockIdx.x * blockDim.x + threadIdx.x;
    if (i < e) atomicAdd(&g_cnt[ei[e + i]], 1);
}

// two-level exclusive scan of g_cnt -> g_rowptr
__global__ void k_scan_a(int n) {
    __shared__ int s[256];
    int i = blockIdx.x * 256 + threadIdx.x;
    int v = (i < n) ? g_cnt[i] : 0;
    s[threadIdx.x] = v;
    __syncthreads();
#pragma unroll
    for (int off = 1; off < 256; off <<= 1) {
        int t = (threadIdx.x >= off) ? s[threadIdx.x - off] : 0;
        __syncthreads();
        s[threadIdx.x] += t;
        __syncthreads();
    }
    if (i < n) g_rowtmp[i] = s[threadIdx.x];
    if (threadIdx.x == 255) g_bsum[blockIdx.x] = s[255];
}

__global__ void k_scan_b(int nblocks) {
    __shared__ int s[256];
    int v = (threadIdx.x < nblocks) ? g_bsum[threadIdx.x] : 0;
    s[threadIdx.x] = v;
    __syncthreads();
#pragma unroll
    for (int off = 1; off < 256; off <<= 1) {
        int t = (threadIdx.x >= off) ? s[threadIdx.x - off] : 0;
        __syncthreads();
        s[threadIdx.x] += t;
        __syncthreads();
    }
    g_boff[threadIdx.x] = s[threadIdx.x] - v;  // exclusive
}

// rowptr + write pointers + dinv (fused)
__global__ void k_scan_c(int n, int e) {
    int i = blockIdx.x * 256 + threadIdx.x;
    if (i < n) {
        int c = g_cnt[i];
        int rp = g_boff[blockIdx.x] + g_rowtmp[i] - c;
        g_rowptr[i] = rp;
        g_wp[i] = rp;
        g_dinv[i] = rsqrtf((float)c + 1.0f);
    }
    if (i == 0) g_rowptr[n] = e;
}

__global__ void k_scatter(const int* __restrict__ ei, int e) {
    int i = blockIdx.x * blockDim.x + threadIdx.x;
    if (i >= e) return;
    int src = ei[i], dst = ei[e + i];
    int pos = atomicAdd(&g_wp[dst], 1);
    float nrm = g_dinv[src] * g_dinv[dst];
    g_edge[pos] = make_int2(src, __float_as_int(nrm));
}

// ---------------------------------------------------------------------------
// GEMM1: h1[n,128] = x[n,128] @ W1[128,128], stored fp16
__global__ void k_gemm1(const float* __restrict__ x, const float* __restrict__ W1, int n) {
    __shared__ float xs[64 * F_IN];
    int base = blockIdx.x * 64;
    const float4* xv = (const float4*)x;
    float4* xsv = (float4*)xs;
    for (int i = threadIdx.x; i < 64 * 32; i += 256) {
        int node = i >> 5, c = i & 31;
        xsv[i] = (base + node < n) ? xv[(size_t)(base + node) * 32 + c]
                                   : make_float4(0.f, 0.f, 0.f, 0.f);
    }
    __syncthreads();
    int j4 = threadIdx.x & 31;   // 4 features
    int ng = threadIdx.x >> 5;   // 8 nodes
    const float4* Wv = (const float4*)W1;
    float acc[8][4];
#pragma unroll
    for (int t = 0; t < 8; t++) { acc[t][0]=acc[t][1]=acc[t][2]=acc[t][3]=0.f; }
#pragma unroll 4
    for (int k = 0; k < F_IN; k++) {
        float4 wk = Wv[k * 32 + j4];
#pragma unroll
        for (int t = 0; t < 8; t++) {
            float xx = xs[(ng * 8 + t) * F_IN + k];
            acc[t][0] += xx * wk.x;
            acc[t][1] += xx * wk.y;
            acc[t][2] += xx * wk.z;
            acc[t][3] += xx * wk.w;
        }
    }
    uint2* h1v = (uint2*)g_h1h;  // 4 halves per uint2
#pragma unroll
    for (int t = 0; t < 8; t++) {
        int node = base + ng * 8 + t;
        if (node < n) {
            __half2 lo = __floats2half2_rn(acc[t][0], acc[t][1]);
            __half2 hi = __floats2half2_rn(acc[t][2], acc[t][3]);
            h1v[(size_t)node * 32 + j4] =
                make_uint2(*(unsigned*)&lo, *(unsigned*)&hi);
        }
    }
}

// ---------------------------------------------------------------------------
// Layer-1 pull aggregation: warp per node, 4 fp16 feats/lane (8B), fp32 acc.
__global__ void k_agg1(int n) {
    int w = (blockIdx.x * blockDim.x + threadIdx.x) >> 5;
    int lane = threadIdx.x & 31;
    if (w >= n) return;
    int beg = g_rowptr[w], end = g_rowptr[w + 1];
    float di = g_dinv[w];
    const uint2* hb = (const uint2*)g_h1h;

    uint2 sv = hb[(size_t)w * 32 + lane];
    float2 s0 = __half22float2(*(__half2*)&sv.x);
    float2 s1 = __half22float2(*(__half2*)&sv.y);
    float s = di * di;
    float4 acc = make_float4(s0.x * s, s0.y * s, s1.x * s, s1.y * s);

    int p = beg;
    for (; p + 4 <= end; p += 4) {
        int2 e0 = g_edge[p], e1 = g_edge[p + 1], e2 = g_edge[p + 2], e3 = g_edge[p + 3];
        uint2 u0 = hb[(size_t)e0.x * 32 + lane];
        uint2 u1 = hb[(size_t)e1.x * 32 + lane];
        uint2 u2 = hb[(size_t)e2.x * 32 + lane];
        uint2 u3 = hb[(size_t)e3.x * 32 + lane];
        float w0 = __int_as_float(e0.y), w1 = __int_as_float(e1.y);
        float w2 = __int_as_float(e2.y), w3 = __int_as_float(e3.y);
        float2 a, b;
        a = __half22float2(*(__half2*)&u0.x); b = __half22float2(*(__half2*)&u0.y);
        acc.x += w0 * a.x; acc.y += w0 * a.y; acc.z += w0 * b.x; acc.w += w0 * b.y;
        a = __half22float2(*(__half2*)&u1.x); b = __half22float2(*(__half2*)&u1.y);
        acc.x += w1 * a.x; acc.y += w1 * a.y; acc.z += w1 * b.x; acc.w += w1 * b.y;
        a = __half22float2(*(__half2*)&u2.x); b = __half22float2(*(__half2*)&u2.y);
        acc.x += w2 * a.x; acc.y += w2 * a.y; acc.z += w2 * b.x; acc.w += w2 * b.y;
        a = __half22float2(*(__half2*)&u3.x); b = __half22float2(*(__half2*)&u3.y);
        acc.x += w3 * a.x; acc.y += w3 * a.y; acc.z += w3 * b.x; acc.w += w3 * b.y;
    }
    for (; p < end; p++) {
        int2 e0 = g_edge[p];
        uint2 u0 = hb[(size_t)e0.x * 32 + lane];
        float w0 = __int_as_float(e0.y);
        float2 a = __half22float2(*(__half2*)&u0.x);
        float2 b = __half22float2(*(__half2*)&u0.y);
        acc.x += w0 * a.x; acc.y += w0 * a.y; acc.z += w0 * b.x; acc.w += w0 * b.y;
    }
    ((float4*)g_agg1)[(size_t)w * 32 + lane] = acc;
}

// ---------------------------------------------------------------------------
// GEMM2: h2[n,64] = relu(agg1 + b1) @ W2[128,64], stored fp16
__global__ void k_gemm2(const float* __restrict__ b1, const float* __restrict__ W2, int n) {
    __shared__ float xs[64 * HID];
    __shared__ float bs[HID];
    int base = blockIdx.x * 64;
    if (threadIdx.x < HID) bs[threadIdx.x] = b1[threadIdx.x];
    __syncthreads();
    for (int i = threadIdx.x; i < 64 * HID; i += 256) {
        int node = i >> 7, k = i & 127;
        float v = (base + node < n) ? g_agg1[(size_t)(base + node) * HID + k] + bs[k] : 0.f;
        xs[i] = fmaxf(v, 0.f);
    }
    __syncthreads();
    int j4 = threadIdx.x & 15;   // 4 features
    int ng = threadIdx.x >> 4;   // 4 nodes
    const float4* Wv = (const float4*)W2;
    float acc[4][4];
#pragma unroll
    for (int t = 0; t < 4; t++) { acc[t][0]=acc[t][1]=acc[t][2]=acc[t][3]=0.f; }
#pragma unroll 4
    for (int k = 0; k < HID; k++) {
        float4 wk = Wv[k * 16 + j4];
#pragma unroll
        for (int t = 0; t < 4; t++) {
            float xx = xs[(ng * 4 + t) * HID + k];
            acc[t][0] += xx * wk.x;
            acc[t][1] += xx * wk.y;
            acc[t][2] += xx * wk.z;
            acc[t][3] += xx * wk.w;
        }
    }
    uint2* h2v = (uint2*)g_h2h;
#pragma unroll
    for (int t = 0; t < 4; t++) {
        int node = base + ng * 4 + t;
        if (node < n) {
            __half2 lo = __floats2half2_rn(acc[t][0], acc[t][1]);
            __half2 hi = __floats2half2_rn(acc[t][2], acc[t][3]);
            h2v[(size_t)node * 16 + j4] =
                make_uint2(*(unsigned*)&lo, *(unsigned*)&hi);
        }
    }
}

// ---------------------------------------------------------------------------
// Layer-2 pull aggregation + bias + ReLU: warp per node, 2 fp16 feats/lane.
__global__ void k_agg2(float* __restrict__ out, const float* __restrict__ b2, int n) {
    int w = (blockIdx.x * blockDim.x + threadIdx.x) >> 5;
    int lane = threadIdx.x & 31;
    if (w >= n) return;
    int beg = g_rowptr[w], end = g_rowptr[w + 1];
    float di = g_dinv[w];
    const unsigned* hb = (const unsigned*)g_h2h;  // one half2 per lane

    unsigned sv = hb[(size_t)w * 32 + lane];
    float2 s0 = __half22float2(*(__half2*)&sv);
    float s = di * di;
    float2 acc = make_float2(s0.x * s, s0.y * s);

    int p = beg;
    for (; p + 4 <= end; p += 4) {
        int2 e0 = g_edge[p], e1 = g_edge[p + 1], e2 = g_edge[p + 2], e3 = g_edge[p + 3];
        unsigned u0 = hb[(size_t)e0.x * 32 + lane];
        unsigned u1 = hb[(size_t)e1.x * 32 + lane];
        unsigned u2 = hb[(size_t)e2.x * 32 + lane];
        unsigned u3 = hb[(size_t)e3.x * 32 + lane];
        float w0 = __int_as_float(e0.y), w1 = __int_as_float(e1.y);
        float w2 = __int_as_float(e2.y), w3 = __int_as_float(e3.y);
        float2 a;
        a = __half22float2(*(__half2*)&u0); acc.x += w0 * a.x; acc.y += w0 * a.y;
        a = __half22float2(*(__half2*)&u1); acc.x += w1 * a.x; acc.y += w1 * a.y;
        a = __half22float2(*(__half2*)&u2); acc.x += w2 * a.x; acc.y += w2 * a.y;
        a = __half22float2(*(__half2*)&u3); acc.x += w3 * a.x; acc.y += w3 * a.y;
    }
    for (; p < end; p++) {
        int2 e0 = g_edge[p];
        unsigned u0 = hb[(size_t)e0.x * 32 + lane];
        float w0 = __int_as_float(e0.y);
        float2 a = __half22float2(*(__half2*)&u0);
        acc.x += w0 * a.x; acc.y += w0 * a.y;
    }
    float bx = b2[lane * 2], by = b2[lane * 2 + 1];
    ((float2*)out)[(size_t)w * 32 + lane] =
        make_float2(fmaxf(acc.x + bx, 0.f), fmaxf(acc.y + by, 0.f));
}

// ---------------------------------------------------------------------------
extern "C" void kernel_launch(void* const* d_in, const int* in_sizes, int n_in,
                              void* d_out, int out_size) {
    const float* x  = (const float*)d_in[0];
    const int*   ei = (const int*)d_in[1];
    const float* W1 = (const float*)d_in[2];
    const float* b1 = (const float*)d_in[3];
    const float* W2 = (const float*)d_in[4];
    const float* b2 = (const float*)d_in[5];
    float* out = (float*)d_out;

    int n = in_sizes[0] / F_IN;
    int e = in_sizes[1] / 2;
    int nb = (n + 255) / 256;

    // CSR build (+degrees +dinv)
    k_zero<<<nb, 256>>>(n);
    k_hist<<<(e + 255) / 256, 256>>>(ei, e);
    k_scan_a<<<nb, 256>>>(n);
    k_scan_b<<<1, 256>>>(nb);
    k_scan_c<<<nb, 256>>>(n, e);
    k_scatter<<<(e + 255) / 256, 256>>>(ei, e);

    // layer 1
    k_gemm1<<<(n + 63) / 64, 256>>>(x, W1, n);
    {
        long long thr = (long long)n * 32;
        k_agg1<<<(int)((thr + 255) / 256), 256>>>(n);
    }
    // layer 2
    k_gemm2<<<(n + 63) / 64, 256>>>(b1, W2, n);
    {
        long long thr = (long long)n * 32;
        k_agg2<<<(int)((thr + 255) / 256), 256>>>(out, b2, n);
    }
}

// round 5
// speedup vs baseline: 2.4698x; 1.0749x over previous
#include <cuda_runtime.h>
#include <cuda_fp16.h>
#include <cstdint>

#define MAXN 50000
#define MAXE 1600000
#define F_IN 128
#define HID  128
#define F_OUT 64

// ---- scratch (device globals; no allocation allowed) ----
__device__ int    g_cnt[MAXN];
__device__ int    g_rowtmp[MAXN];
__device__ int    g_bsum[256];
__device__ int    g_rowptr[MAXN + 1];
__device__ int    g_wp[MAXN];
__device__ float  g_dinv[MAXN];
__device__ int2   g_edge[MAXE];                 // .x = src, .y = bits(norm)
__device__ __half g_h1h[(size_t)MAXN * HID];    // fp16 x@W1 (gather operand)
__device__ float  g_agg1[(size_t)MAXN * HID];   // fp32 aggregated layer-1
__device__ __half g_h2h[(size_t)MAXN * F_OUT];  // fp16 layer-2 pre-agg

// ---------------------------------------------------------------------------
__global__ void k_hist(const int* __restrict__ ei, int e) {
    int i = blockIdx.x * blockDim.x + threadIdx.x;
    if (i < e) atomicAdd(&g_cnt[ei[e + i]], 1);
}

// block-local inclusive scan of g_cnt; block totals to g_bsum
__global__ void k_scan_a(int n) {
    __shared__ int s[256];
    int i = blockIdx.x * 256 + threadIdx.x;
    int v = (i < n) ? g_cnt[i] : 0;
    s[threadIdx.x] = v;
    __syncthreads();
#pragma unroll
    for (int off = 1; off < 256; off <<= 1) {
        int t = (threadIdx.x >= off) ? s[threadIdx.x - off] : 0;
        __syncthreads();
        s[threadIdx.x] += t;
        __syncthreads();
    }
    if (i < n) g_rowtmp[i] = s[threadIdx.x];
    if (threadIdx.x == 255) g_bsum[blockIdx.x] = s[255];
}

// fused: per-block reduce of prior block sums + rowptr + wp + dinv
__global__ void k_scan_c(int n, int e) {
    __shared__ int red[8];
    __shared__ int s_off;
    int partial = 0;
    for (int j = threadIdx.x; j < blockIdx.x; j += 256) partial += g_bsum[j];
#pragma unroll
    for (int o = 16; o; o >>= 1) partial += __shfl_down_sync(0xffffffffu, partial, o);
    if ((threadIdx.x & 31) == 0) red[threadIdx.x >> 5] = partial;
    __syncthreads();
    if (threadIdx.x == 0) {
        int t = 0;
#pragma unroll
        for (int k = 0; k < 8; k++) t += red[k];
        s_off = t;
    }
    __syncthreads();
    int i = blockIdx.x * 256 + threadIdx.x;
    if (i < n) {
        int c = g_cnt[i];
        int rp = s_off + g_rowtmp[i] - c;  // exclusive prefix
        g_rowptr[i] = rp;
        g_wp[i] = rp;
        g_dinv[i] = rsqrtf((float)c + 1.0f);
    }
    if (i == 0) g_rowptr[n] = e;
}

__global__ void k_scatter(const int* __restrict__ ei, int e) {
    int i = blockIdx.x * blockDim.x + threadIdx.x;
    if (i >= e) return;
    int src = ei[i], dst = ei[e + i];
    int pos = atomicAdd(&g_wp[dst], 1);
    float nrm = g_dinv[src] * g_dinv[dst];
    g_edge[pos] = make_int2(src, __float_as_int(nrm));
}

// ---------------------------------------------------------------------------
// GEMM1: h1[n,128] = x[n,128] @ W1[128,128], stored fp16
__global__ void k_gemm1(const float* __restrict__ x, const float* __restrict__ W1, int n) {
    __shared__ float xs[64 * F_IN];
    int base = blockIdx.x * 64;
    const float4* xv = (const float4*)x;
    float4* xsv = (float4*)xs;
    for (int i = threadIdx.x; i < 64 * 32; i += 256) {
        int node = i >> 5, c = i & 31;
        xsv[i] = (base + node < n) ? xv[(size_t)(base + node) * 32 + c]
                                   : make_float4(0.f, 0.f, 0.f, 0.f);
    }
    __syncthreads();
    int j4 = threadIdx.x & 31;   // 4 features
    int ng = threadIdx.x >> 5;   // 8 nodes
    const float4* Wv = (const float4*)W1;
    float acc[8][4];
#pragma unroll
    for (int t = 0; t < 8; t++) { acc[t][0]=acc[t][1]=acc[t][2]=acc[t][3]=0.f; }
#pragma unroll 4
    for (int k = 0; k < F_IN; k++) {
        float4 wk = Wv[k * 32 + j4];
#pragma unroll
        for (int t = 0; t < 8; t++) {
            float xx = xs[(ng * 8 + t) * F_IN + k];
            acc[t][0] += xx * wk.x;
            acc[t][1] += xx * wk.y;
            acc[t][2] += xx * wk.z;
            acc[t][3] += xx * wk.w;
        }
    }
    uint2* h1v = (uint2*)g_h1h;
#pragma unroll
    for (int t = 0; t < 8; t++) {
        int node = base + ng * 8 + t;
        if (node < n) {
            __half2 lo = __floats2half2_rn(acc[t][0], acc[t][1]);
            __half2 hi = __floats2half2_rn(acc[t][2], acc[t][3]);
            h1v[(size_t)node * 32 + j4] =
                make_uint2(*(unsigned*)&lo, *(unsigned*)&hi);
        }
    }
}

// ---------------------------------------------------------------------------
// Layer-1 pull aggregation: warp per node, 4 fp16 feats/lane, fp32 acc.
__global__ void k_agg1(int n) {
    int w = (blockIdx.x * blockDim.x + threadIdx.x) >> 5;
    int lane = threadIdx.x & 31;
    if (w >= n) return;
    int beg = g_rowptr[w], end = g_rowptr[w + 1];
    float di = g_dinv[w];
    const uint2* hb = (const uint2*)g_h1h;

    uint2 sv = hb[(size_t)w * 32 + lane];
    float2 s0 = __half22float2(*(__half2*)&sv.x);
    float2 s1 = __half22float2(*(__half2*)&sv.y);
    float s = di * di;
    float4 acc = make_float4(s0.x * s, s0.y * s, s1.x * s, s1.y * s);

    int p = beg;
    for (; p + 4 <= end; p += 4) {
        int2 e0 = g_edge[p], e1 = g_edge[p + 1], e2 = g_edge[p + 2], e3 = g_edge[p + 3];
        uint2 u0 = hb[(size_t)e0.x * 32 + lane];
        uint2 u1 = hb[(size_t)e1.x * 32 + lane];
        uint2 u2 = hb[(size_t)e2.x * 32 + lane];
        uint2 u3 = hb[(size_t)e3.x * 32 + lane];
        float w0 = __int_as_float(e0.y), w1 = __int_as_float(e1.y);
        float w2 = __int_as_float(e2.y), w3 = __int_as_float(e3.y);
        float2 a, b;
        a = __half22float2(*(__half2*)&u0.x); b = __half22float2(*(__half2*)&u0.y);
        acc.x += w0 * a.x; acc.y += w0 * a.y; acc.z += w0 * b.x; acc.w += w0 * b.y;
        a = __half22float2(*(__half2*)&u1.x); b = __half22float2(*(__half2*)&u1.y);
        acc.x += w1 * a.x; acc.y += w1 * a.y; acc.z += w1 * b.x; acc.w += w1 * b.y;
        a = __half22float2(*(__half2*)&u2.x); b = __half22float2(*(__half2*)&u2.y);
        acc.x += w2 * a.x; acc.y += w2 * a.y; acc.z += w2 * b.x; acc.w += w2 * b.y;
        a = __half22float2(*(__half2*)&u3.x); b = __half22float2(*(__half2*)&u3.y);
        acc.x += w3 * a.x; acc.y += w3 * a.y; acc.z += w3 * b.x; acc.w += w3 * b.y;
    }
    for (; p < end; p++) {
        int2 e0 = g_edge[p];
        uint2 u0 = hb[(size_t)e0.x * 32 + lane];
        float w0 = __int_as_float(e0.y);
        float2 a = __half22float2(*(__half2*)&u0.x);
        float2 b = __half22float2(*(__half2*)&u0.y);
        acc.x += w0 * a.x; acc.y += w0 * a.y; acc.z += w0 * b.x; acc.w += w0 * b.y;
    }
    ((float4*)g_agg1)[(size_t)w * 32 + lane] = acc;
}

// ---------------------------------------------------------------------------
// GEMM2: h2[n,64] = relu(agg1 + b1) @ W2[128,64], stored fp16
__global__ void k_gemm2(const float* __restrict__ b1, const float* __restrict__ W2, int n) {
    __shared__ float xs[64 * HID];
    __shared__ float bs[HID];
    int base = blockIdx.x * 64;
    if (threadIdx.x < HID) bs[threadIdx.x] = b1[threadIdx.x];
    __syncthreads();
    for (int i = threadIdx.x; i < 64 * HID; i += 256) {
        int node = i >> 7, k = i & 127;
        float v = (base + node < n) ? g_agg1[(size_t)(base + node) * HID + k] + bs[k] : 0.f;
        xs[i] = fmaxf(v, 0.f);
    }
    __syncthreads();
    int j4 = threadIdx.x & 15;   // 4 features
    int ng = threadIdx.x >> 4;   // 4 nodes
    const float4* Wv = (const float4*)W2;
    float acc[4][4];
#pragma unroll
    for (int t = 0; t < 4; t++) { acc[t][0]=acc[t][1]=acc[t][2]=acc[t][3]=0.f; }
#pragma unroll 4
    for (int k = 0; k < HID; k++) {
        float4 wk = Wv[k * 16 + j4];
#pragma unroll
        for (int t = 0; t < 4; t++) {
            float xx = xs[(ng * 4 + t) * HID + k];
            acc[t][0] += xx * wk.x;
            acc[t][1] += xx * wk.y;
            acc[t][2] += xx * wk.z;
            acc[t][3] += xx * wk.w;
        }
    }
    uint2* h2v = (uint2*)g_h2h;
#pragma unroll
    for (int t = 0; t < 4; t++) {
        int node = base + ng * 4 + t;
        if (node < n) {
            __half2 lo = __floats2half2_rn(acc[t][0], acc[t][1]);
            __half2 hi = __floats2half2_rn(acc[t][2], acc[t][3]);
            h2v[(size_t)node * 16 + j4] =
                make_uint2(*(unsigned*)&lo, *(unsigned*)&hi);
        }
    }
}

// ---------------------------------------------------------------------------
// Layer-2 pull aggregation + bias + ReLU: warp per node, 2 fp16 feats/lane.
__global__ void k_agg2(float* __restrict__ out, const float* __restrict__ b2, int n) {
    int w = (blockIdx.x * blockDim.x + threadIdx.x) >> 5;
    int lane = threadIdx.x & 31;
    if (w >= n) return;
    int beg = g_rowptr[w], end = g_rowptr[w + 1];
    float di = g_dinv[w];
    const unsigned* hb = (const unsigned*)g_h2h;

    unsigned sv = hb[(size_t)w * 32 + lane];
    float2 s0 = __half22float2(*(__half2*)&sv);
    float s = di * di;
    float2 acc = make_float2(s0.x * s, s0.y * s);

    int p = beg;
    for (; p + 4 <= end; p += 4) {
        int2 e0 = g_edge[p], e1 = g_edge[p + 1], e2 = g_edge[p + 2], e3 = g_edge[p + 3];
        unsigned u0 = hb[(size_t)e0.x * 32 + lane];
        unsigned u1 = hb[(size_t)e1.x * 32 + lane];
        unsigned u2 = hb[(size_t)e2.x * 32 + lane];
        unsigned u3 = hb[(size_t)e3.x * 32 + lane];
        float w0 = __int_as_float(e0.y), w1 = __int_as_float(e1.y);
        float w2 = __int_as_float(e2.y), w3 = __int_as_float(e3.y);
        float2 a;
        a = __half22float2(*(__half2*)&u0); acc.x += w0 * a.x; acc.y += w0 * a.y;
        a = __half22float2(*(__half2*)&u1); acc.x += w1 * a.x; acc.y += w1 * a.y;
        a = __half22float2(*(__half2*)&u2); acc.x += w2 * a.x; acc.y += w2 * a.y;
        a = __half22float2(*(__half2*)&u3); acc.x += w3 * a.x; acc.y += w3 * a.y;
    }
    for (; p < end; p++) {
        int2 e0 = g_edge[p];
        unsigned u0 = hb[(size_t)e0.x * 32 + lane];
        float w0 = __int_as_float(e0.y);
        float2 a = __half22float2(*(__half2*)&u0);
        acc.x += w0 * a.x; acc.y += w0 * a.y;
    }
    float bx = b2[lane * 2], by = b2[lane * 2 + 1];
    ((float2*)out)[(size_t)w * 32 + lane] =
        make_float2(fmaxf(acc.x + bx, 0.f), fmaxf(acc.y + by, 0.f));
}

// ---------------------------------------------------------------------------
extern "C" void kernel_launch(void* const* d_in, const int* in_sizes, int n_in,
                              void* d_out, int out_size) {
    const float* x  = (const float*)d_in[0];
    const int*   ei = (const int*)d_in[1];
    const float* W1 = (const float*)d_in[2];
    const float* b1 = (const float*)d_in[3];
    const float* W2 = (const float*)d_in[4];
    const float* b2 = (const float*)d_in[5];
    float* out = (float*)d_out;

    int n = in_sizes[0] / F_IN;
    int e = in_sizes[1] / 2;
    int nb = (n + 255) / 256;

    // one-time infra (created on first call = correctness run, outside capture;
    // identical launch sequence every call)
    static cudaStream_t s2 = nullptr;
    static cudaEvent_t evRoot = nullptr, evJoin = nullptr;
    if (!s2) {
        cudaStreamCreateWithFlags(&s2, cudaStreamNonBlocking);
        cudaEventCreateWithFlags(&evRoot, cudaEventDisableTiming);
        cudaEventCreateWithFlags(&evJoin, cudaEventDisableTiming);
    }

    void* cntPtr = nullptr;
    cudaGetSymbolAddress(&cntPtr, g_cnt);

    // fork: GEMM1 (x,W1 only) runs concurrently with the CSR build
    cudaEventRecord(evRoot, 0);
    cudaStreamWaitEvent(s2, evRoot, 0);
    k_gemm1<<<(n + 63) / 64, 256, 0, s2>>>(x, W1, n);
    cudaEventRecord(evJoin, s2);

    // CSR build chain on capture (default) stream
    cudaMemsetAsync(cntPtr, 0, (size_t)n * sizeof(int), 0);
    k_hist<<<(e + 255) / 256, 256>>>(ei, e);
    k_scan_a<<<nb, 256>>>(n);
    k_scan_c<<<nb, 256>>>(n, e);
    k_scatter<<<(e + 255) / 256, 256>>>(ei, e);

    // join: agg1 needs both h1 (s2) and CSR (default)
    cudaStreamWaitEvent(0, evJoin, 0);
    {
        long long thr = (long long)n * 32;
        k_agg1<<<(int)((thr + 255) / 256), 256>>>(n);
    }
    k_gemm2<<<(n + 63) / 64, 256>>>(b1, W2, n);
    {
        long long thr = (long long)n * 32;
        k_agg2<<<(int)((thr + 255) / 256), 256>>>(out, b2, n);
    }
}